// round 1
// baseline (speedup 1.0000x reference)
#include <cuda_runtime.h>

typedef unsigned long long ull;

// 5x5x3x3 conv weights, broadcast-uniform across all threads -> constant bank (LDCU path)
__constant__ float cW[225];

// 201 MB ping-pong scratch (allocation-free rule: __device__ global)
__device__ float g_buf[16u * 3u * 1024u * 1024u];

__device__ __forceinline__ ull pack2(float lo, float hi) {
    ull r;
    asm("mov.b64 %0, {%1, %2};" : "=l"(r) : "f"(lo), "f"(hi));
    return r;
}

__device__ __forceinline__ float2 unpack2(ull v) {
    float2 r;
    asm("mov.b64 {%0, %1}, %2;" : "=f"(r.x), "=f"(r.y) : "l"(v));
    return r;
}

// packed fp32x2 FMA (FFMA2) -- only reachable via PTX fma.rn.f32x2 on sm_103a
__device__ __forceinline__ void fma2(ull& d, ull a, ull b) {
    asm("fma.rn.f32x2 %0, %1, %2, %0;" : "+l"(d) : "l"(a), "l"(b));
}

// Block: 128 threads (16 x, 8 y). Tile: 128 cols x 16 rows x 3 channels.
// Each thread: 8 consecutive cols x 2 rows (r, r+8, packed as f32x2) x 3 out-channels.
// SMEM input tile stored as vertical float2 pairs: sm[ch][p][xi] = (row rb+p-2, row rb+p+6),
// so the pair needed for (ty, ky) is exactly p = ty + ky, xi = tx*8 + t + kx.
__global__ void __launch_bounds__(128) ca_step(const float* __restrict__ src,
                                               float* __restrict__ dst)
{
    __shared__ __align__(16) float2 sm[3][12][132];

    const int tx  = threadIdx.x;
    const int ty  = threadIdx.y;
    const int tid = ty * 16 + tx;
    const int xb  = blockIdx.x * 128;
    const int rb  = blockIdx.y * 16;
    const int img = blockIdx.z;

    // ---- load input tile (3ch x 12 pair-rows x 132 cols), circular wrap via &1023 ----
    #pragma unroll 1
    for (int i = tid; i < 3 * 12 * 132; i += 128) {
        int ch  = i / 1584;
        int rem = i - ch * 1584;
        int p   = rem / 132;
        int xi  = rem - p * 132;
        int col = (xb + xi - 2) & 1023;
        int rA  = (rb + p - 2) & 1023;
        int rB  = (rb + p + 6) & 1023;
        const float* base = src + (((size_t)(img * 3 + ch)) << 20);
        sm[ch][p][xi] = make_float2(__ldg(base + (rA << 10) + col),
                                    __ldg(base + (rB << 10) + col));
    }
    __syncthreads();

    // ---- accumulate conv y for 3 out-channels x 8 cols, rows packed in f32x2 ----
    ull acc[3][8];
    #pragma unroll
    for (int co = 0; co < 3; ++co)
        #pragma unroll
        for (int t = 0; t < 8; ++t)
            acc[co][t] = 0ull;  // (0.0f, 0.0f)

    #pragma unroll 1
    for (int ci = 0; ci < 3; ++ci) {
        #pragma unroll
        for (int ky = 0; ky < 5; ++ky) {
            // 12 f32x2 pairs covering cols [tx*8-2 .. tx*8+9] (+2 offset baked into layout)
            const ulonglong2* v =
                reinterpret_cast<const ulonglong2*>(&sm[ci][ty + ky][tx * 8]);
            ull rv[12];
            #pragma unroll
            for (int k = 0; k < 6; ++k) {
                ulonglong2 q = v[k];   // 16B-aligned LDS.128
                rv[2 * k]     = q.x;
                rv[2 * k + 1] = q.y;
            }
            #pragma unroll
            for (int co = 0; co < 3; ++co) {
                #pragma unroll
                for (int kx = 0; kx < 5; ++kx) {
                    float w = cW[(co * 3 + ci) * 25 + ky * 5 + kx];  // LDCU (uniform)
                    ull  wp = pack2(w, w);
                    #pragma unroll
                    for (int t = 0; t < 8; ++t)
                        fma2(acc[co][t], rv[t + kx], wp);
                }
            }
        }
    }

    // ---- epilogue: out = clip(x + 0.1*relu(y), 0, 1) ; x comes from smem pair p=ty+2 ----
    const int ocol = xb + tx * 8;
    const int r0   = rb + ty;
    const int r1   = r0 + 8;

    #pragma unroll
    for (int co = 0; co < 3; ++co) {
        float lo[8], hi[8];
        #pragma unroll
        for (int t = 0; t < 8; ++t) {
            float2 y  = unpack2(acc[co][t]);
            float2 xp = sm[co][ty + 2][tx * 8 + t + 2];
            lo[t] = __saturatef(fmaf(fmaxf(y.x, 0.0f), 0.1f, xp.x));
            hi[t] = __saturatef(fmaf(fmaxf(y.y, 0.0f), 0.1f, xp.y));
        }
        float* ob = dst + (((size_t)(img * 3 + co)) << 20);
        *reinterpret_cast<float4*>(ob + (r0 << 10) + ocol)     = make_float4(lo[0], lo[1], lo[2], lo[3]);
        *reinterpret_cast<float4*>(ob + (r0 << 10) + ocol + 4) = make_float4(lo[4], lo[5], lo[6], lo[7]);
        *reinterpret_cast<float4*>(ob + (r1 << 10) + ocol)     = make_float4(hi[0], hi[1], hi[2], hi[3]);
        *reinterpret_cast<float4*>(ob + (r1 << 10) + ocol + 4) = make_float4(hi[4], hi[5], hi[6], hi[7]);
    }
}

extern "C" void kernel_launch(void* const* d_in, const int* in_sizes, int n_in,
                              void* d_out, int out_size)
{
    const float* x = (const float*)d_in[0];
    const float* W = (const float*)d_in[1];
    float* out = (float*)d_out;

    float* scratch = nullptr;
    cudaGetSymbolAddress((void**)&scratch, g_buf);

    // weights -> constant bank (d2d async memcpy; graph-capturable)
    cudaMemcpyToSymbolAsync(cW, W, 225 * sizeof(float), 0, cudaMemcpyDeviceToDevice, 0);

    dim3 grid(8, 64, 16);   // 1024/128 cols, 1024/16 rows, 16 images
    dim3 block(16, 8);

    const float* src = x;
    for (int s = 0; s < 10; ++s) {
        float* dst = (s & 1) ? out : scratch;  // step 9 (last) lands in d_out
        ca_step<<<grid, block>>>(src, dst);
        src = dst;
    }
}

// round 2
// speedup vs baseline: 2.0575x; 2.0575x over previous
#include <cuda_runtime.h>

typedef unsigned long long ull;

// 201 MB ping-pong scratch (allocation-free rule: __device__ global)
__device__ float g_buf[16u * 3u * 1024u * 1024u];
// pre-packed (w,w) f32x2 weights, layout [ci][kx][co*5+ky] padded to 16
__device__ ull   g_wpack[240];

__device__ __forceinline__ ull pack2(float lo, float hi) {
    ull r;
    asm("mov.b64 %0, {%1, %2};" : "=l"(r) : "f"(lo), "f"(hi));
    return r;
}
__device__ __forceinline__ float2 unpack2(ull v) {
    float2 r;
    asm("mov.b64 {%0, %1}, %2;" : "=f"(r.x), "=f"(r.y) : "l"(v));
    return r;
}
// packed fp32x2 FMA (FFMA2) -- only reachable via PTX fma.rn.f32x2
__device__ __forceinline__ void fma2(ull& d, ull a, ull b) {
    asm("fma.rn.f32x2 %0, %1, %2, %0;" : "+l"(d) : "l"(a), "l"(b));
}

// prep: broadcast-pack weights once; W is OIHW [co][ci][ky][kx] = [3][3][5][5]
__global__ void pack_w(const float* __restrict__ W) {
    int i = threadIdx.x;
    if (i >= 240) return;
    int ci = i / 80;
    int r  = i - ci * 80;
    int kx = r / 16;
    int s  = r - kx * 16;
    float w = 0.0f;
    if (s < 15) {
        int co = s / 5;
        int ky = s - co * 5;
        w = W[co * 75 + ci * 25 + ky * 5 + kx];
    }
    g_wpack[i] = pack2(w, w);
}

// Block: 128 threads. Tile: 128 cols x 16 rows x 3 channels.
// Thread owns ONE column (col = xb + tid) and 16 rows as 8 vertical f32x2 pairs
// (rows r, r+8).  smem pair layout: smx[ch][p][xi] = (row rb+p-2, row rb+p+6),
// so output pair p_out with tap ky reads input pair p_out+ky at col tid+kx.
// LDS.64 window loads have 8B lane stride -> conflict-free.
__global__ void __launch_bounds__(128, 5) ca_step(const float* __restrict__ src,
                                                  float* __restrict__ dst)
{
    __shared__ __align__(16) float2 smx[3][12][132];
    __shared__ __align__(16) ull    wS[240];

    const int tid = threadIdx.x;
    const int xb  = blockIdx.x * 128;
    const int rb  = blockIdx.y * 16;
    const int img = blockIdx.z;

    // ---- weights -> smem (broadcast source for the hot loop) ----
    if (tid < 120) {
        wS[tid]       = g_wpack[tid];
        wS[tid + 120] = g_wpack[tid + 120];
    }

    // ---- vectorized interior tile load: 36 pair-rows x 32 float4 groups ----
    #pragma unroll 1
    for (int i = tid; i < 1152; i += 128) {
        int ch  = i / 384;
        int rem = i - ch * 384;
        int p   = rem >> 5;
        int v   = rem & 31;
        int rA  = (rb + p - 2) & 1023;
        int rB  = (rA + 8) & 1023;
        const float* base = src + (((size_t)(img * 3 + ch)) << 20) + xb + v * 4;
        float4 a = *reinterpret_cast<const float4*>(base + (rA << 10));
        float4 b = *reinterpret_cast<const float4*>(base + (rB << 10));
        float4* s = reinterpret_cast<float4*>(&smx[ch][p][2 + v * 4]);
        s[0] = make_float4(a.x, b.x, a.y, b.y);
        s[1] = make_float4(a.z, b.z, a.w, b.w);
    }
    // ---- halo columns xi in {0,1,130,131} (wrap) : 3ch x 12p x 4 = 144 ----
    #pragma unroll 1
    for (int i = tid; i < 144; i += 128) {
        int ch  = i / 48;
        int rem = i - ch * 48;
        int p   = rem >> 2;
        int j   = rem & 3;
        int xi  = (j < 2) ? j : (j + 128);
        int col = (xb + xi - 2) & 1023;
        int rA  = (rb + p - 2) & 1023;
        int rB  = (rA + 8) & 1023;
        const float* base = src + (((size_t)(img * 3 + ch)) << 20);
        smx[ch][p][xi] = make_float2(__ldg(base + (rA << 10) + col),
                                     __ldg(base + (rB << 10) + col));
    }
    __syncthreads();

    // ---- conv accumulation: 3 out-channels x 8 row-pairs, packed f32x2 ----
    ull acc[3][8];
    #pragma unroll
    for (int co = 0; co < 3; ++co)
        #pragma unroll
        for (int p = 0; p < 8; ++p)
            acc[co][p] = 0ull;

    #pragma unroll 1
    for (int ci = 0; ci < 3; ++ci) {
        #pragma unroll 1
        for (int kx = 0; kx < 5; ++kx) {
            // 12 conflict-free LDS.64: column tid+kx, all pair-rows
            ull rv[12];
            #pragma unroll
            for (int p = 0; p < 12; ++p)
                rv[p] = *reinterpret_cast<const ull*>(&smx[ci][p][tid + kx]);

            const ull* wrow = &wS[ci * 80 + kx * 16];
            #pragma unroll
            for (int co = 0; co < 3; ++co) {
                #pragma unroll
                for (int ky = 0; ky < 5; ++ky) {
                    ull wp = wrow[co * 5 + ky];   // broadcast LDS.64
                    #pragma unroll
                    for (int p = 0; p < 8; ++p)
                        fma2(acc[co][p], rv[p + ky], wp);
                }
            }
        }
    }

    // ---- epilogue: out = clip(x + 0.1*relu(y), 0, 1) ----
    const int col = xb + tid;
    #pragma unroll
    for (int co = 0; co < 3; ++co) {
        float* ob = dst + (((size_t)(img * 3 + co)) << 20) + col;
        #pragma unroll
        for (int p = 0; p < 8; ++p) {
            float2 y  = unpack2(acc[co][p]);
            float2 xp = smx[co][p + 2][tid + 2];   // (row rb+p, row rb+p+8)
            ob[(rb + p)     << 10] = __saturatef(fmaf(fmaxf(y.x, 0.0f), 0.1f, xp.x));
            ob[(rb + p + 8) << 10] = __saturatef(fmaf(fmaxf(y.y, 0.0f), 0.1f, xp.y));
        }
    }
}

extern "C" void kernel_launch(void* const* d_in, const int* in_sizes, int n_in,
                              void* d_out, int out_size)
{
    const float* x = (const float*)d_in[0];
    const float* W = (const float*)d_in[1];
    float* out = (float*)d_out;

    float* scratch = nullptr;
    cudaGetSymbolAddress((void**)&scratch, g_buf);

    pack_w<<<1, 256>>>(W);

    dim3 grid(8, 64, 16);   // 1024/128 cols, 1024/16 rows, 16 images
    dim3 block(128);

    const float* src = x;
    for (int s = 0; s < 10; ++s) {
        float* dst = (s & 1) ? out : scratch;  // step 9 (last) lands in d_out
        ca_step<<<grid, block>>>(src, dst);
        src = dst;
    }
}